// round 17
// baseline (speedup 1.0000x reference)
#include <cuda_runtime.h>
#include <cuda_bf16.h>
#include <math.h>
#include <stdint.h>

// Problem constants
#define BB 2
#define TT 2048
#define CC 2048
#define HH 16
#define DD 128
#define NTOK (BB*TT)      // 4096
#define C3 (3*CC)         // 6144

// fp32 scratch
__device__ float g_qkv[(size_t)NTOK * C3];
// bf16 hi/lo scratch
__device__ __nv_bfloat16 g_xh[(size_t)NTOK * CC],  g_xl[(size_t)NTOK * CC];
__device__ __nv_bfloat16 g_wqh[(size_t)C3 * CC],   g_wql[(size_t)C3 * CC];
__device__ __nv_bfloat16 g_wph[(size_t)CC * CC],   g_wpl[(size_t)CC * CC];
__device__ __nv_bfloat16 g_ah[(size_t)NTOK * CC],  g_al[(size_t)NTOK * CC];

// ===========================================================================
// helpers
// ===========================================================================
__device__ __forceinline__ uint32_t smem_to_u32(const void* p) {
    uint32_t a;
    asm("{ .reg .u64 t; cvta.to.shared.u64 t, %1; cvt.u32.u64 %0, t; }"
        : "=r"(a) : "l"(p));
    return a;
}
__device__ __forceinline__ void ldmatrix_x4(uint32_t* r, uint32_t addr) {
    asm volatile("ldmatrix.sync.aligned.m8n8.x4.shared.b16 {%0,%1,%2,%3}, [%4];"
                 : "=r"(r[0]), "=r"(r[1]), "=r"(r[2]), "=r"(r[3]) : "r"(addr));
}
__device__ __forceinline__ void ldmatrix_x4t(uint32_t* r, uint32_t addr) {
    asm volatile("ldmatrix.sync.aligned.m8n8.x4.trans.shared.b16 {%0,%1,%2,%3}, [%4];"
                 : "=r"(r[0]), "=r"(r[1]), "=r"(r[2]), "=r"(r[3]) : "r"(addr));
}
__device__ __forceinline__ void ldmatrix_x2(uint32_t* r, uint32_t addr) {
    asm volatile("ldmatrix.sync.aligned.m8n8.x2.shared.b16 {%0,%1}, [%2];"
                 : "=r"(r[0]), "=r"(r[1]) : "r"(addr));
}
__device__ __forceinline__ void mma_bf16(float* c, const uint32_t* a, const uint32_t* b) {
    asm volatile(
        "mma.sync.aligned.m16n8k16.row.col.f32.bf16.bf16.f32 "
        "{%0,%1,%2,%3}, {%4,%5,%6,%7}, {%8,%9}, {%0,%1,%2,%3};"
        : "+f"(c[0]), "+f"(c[1]), "+f"(c[2]), "+f"(c[3])
        : "r"(a[0]), "r"(a[1]), "r"(a[2]), "r"(a[3]), "r"(b[0]), "r"(b[1]));
}
__device__ __forceinline__ uint32_t pack_bf16(float a, float b) {
    __nv_bfloat162 t(__float2bfloat16_rn(a), __float2bfloat16_rn(b));
    return *(uint32_t*)&t;
}
// Fast exp on the FMA pipe (no MUFU): degree-5 2^f poly, |rel err| ~2e-6.
// Valid for x <= ~0 (clamped at -80 so masked -1e30 scores flush to ~0).
__device__ __forceinline__ float fast_exp(float x) {
    x = fmaxf(x, -80.0f);
    float y = x * 1.4426950408889634f;
    float r = y + 12582912.0f;                  // round-to-nearest-int magic
    int   n = __float_as_int(r) - 0x4B400000;   // integer part
    float f = y - (r - 12582912.0f);            // frac in [-0.5, 0.5]
    float p = 1.3333558146e-3f;
    p = fmaf(p, f, 9.6181291076e-3f);
    p = fmaf(p, f, 5.5504108664e-2f);
    p = fmaf(p, f, 2.4022650696e-1f);
    p = fmaf(p, f, 6.9314718056e-1f);
    p = fmaf(p, f, 1.0f);
    return __int_as_float(__float_as_int(p) + (n << 23));
}
#define CP_ASYNC16(dst_u32, src) \
    asm volatile("cp.async.cg.shared.global [%0], [%1], 16;" \
                 :: "r"(dst_u32), "l"(src) : "memory")
#define CP_COMMIT() asm volatile("cp.async.commit_group;" ::: "memory")
#define CP_WAIT(n)  asm volatile("cp.async.wait_group %0;" :: "n"(n) : "memory")

// ===========================================================================
// fp32 -> bf16 hi/lo split
// ===========================================================================
__global__ __launch_bounds__(256) void split_bf16(
    const float* __restrict__ in, __nv_bfloat16* __restrict__ hi,
    __nv_bfloat16* __restrict__ lo, int n4)
{
    int i = blockIdx.x * blockDim.x + threadIdx.x;
    if (i >= n4) return;
    float4 v = ((const float4*)in)[i];
    __nv_bfloat16 h0 = __float2bfloat16_rn(v.x);
    __nv_bfloat16 h1 = __float2bfloat16_rn(v.y);
    __nv_bfloat16 h2 = __float2bfloat16_rn(v.z);
    __nv_bfloat16 h3 = __float2bfloat16_rn(v.w);
    __nv_bfloat16 l0 = __float2bfloat16_rn(v.x - __bfloat162float(h0));
    __nv_bfloat16 l1 = __float2bfloat16_rn(v.y - __bfloat162float(h1));
    __nv_bfloat16 l2 = __float2bfloat16_rn(v.z - __bfloat162float(h2));
    __nv_bfloat16 l3 = __float2bfloat16_rn(v.w - __bfloat162float(h3));
    ((__nv_bfloat162*)hi)[i*2]     = __nv_bfloat162(h0, h1);
    ((__nv_bfloat162*)hi)[i*2 + 1] = __nv_bfloat162(h2, h3);
    ((__nv_bfloat162*)lo)[i*2]     = __nv_bfloat162(l0, l1);
    ((__nv_bfloat162*)lo)[i*2 + 1] = __nv_bfloat162(l2, l3);
}

// ===========================================================================
// mma.sync bf16 GEMM (hi/lo 3-term), CTA 128x128, BK=32, 256 thr, 8 warps.
// ===========================================================================
#define MM_PAD 40
#define MM_TILE (128 * MM_PAD * 2)
#define MM_BUF  (4 * MM_TILE)
#define MM_SMEM (2 * MM_BUF)

__global__ __launch_bounds__(256, 2) void gemm_mma(
    const __nv_bfloat16* __restrict__ Ah, const __nv_bfloat16* __restrict__ Al,
    const __nv_bfloat16* __restrict__ Bh, const __nv_bfloat16* __restrict__ Bl,
    float* __restrict__ C, int M, int N, int K)
{
    extern __shared__ __align__(16) char smem[];
    const uint32_t sb = smem_to_u32(smem);
    const int tid = threadIdx.x;
    const int lane = tid & 31;
    const int wid = tid >> 5;
    const int warp_m = wid & 1;
    const int warp_n = wid >> 1;
    const int m0 = blockIdx.y * 128;
    const int n0 = blockIdx.x * 128;

    float acc[4][4][4];
#pragma unroll
    for (int i = 0; i < 4; i++)
#pragma unroll
        for (int j = 0; j < 4; j++)
#pragma unroll
            for (int k = 0; k < 4; k++) acc[i][j][k] = 0.f;

    const int r0 = tid >> 2, ch0 = (tid & 3);
    const int r1 = (tid + 256) >> 2, ch1 = ((tid + 256) & 3);

    auto issue_loads = [&](int it) {
        const int kb = it * 32;
        const uint32_t b = sb + (it & 1) * MM_BUF;
        const uint32_t d0 = b + r0 * 80 + ch0 * 16;
        const uint32_t d1 = b + r1 * 80 + ch1 * 16;
        const size_t sa0 = (size_t)(m0 + r0) * K + kb + ch0 * 8;
        const size_t sa1 = (size_t)(m0 + r1) * K + kb + ch1 * 8;
        const size_t sb0 = (size_t)(n0 + r0) * K + kb + ch0 * 8;
        const size_t sb1 = (size_t)(n0 + r1) * K + kb + ch1 * 8;
        CP_ASYNC16(d0,                 Ah + sa0);
        CP_ASYNC16(d1,                 Ah + sa1);
        CP_ASYNC16(d0 + MM_TILE,       Al + sa0);
        CP_ASYNC16(d1 + MM_TILE,       Al + sa1);
        CP_ASYNC16(d0 + 2 * MM_TILE,   Bh + sb0);
        CP_ASYNC16(d1 + 2 * MM_TILE,   Bh + sb1);
        CP_ASYNC16(d0 + 3 * MM_TILE,   Bl + sb0);
        CP_ASYNC16(d1 + 3 * MM_TILE,   Bl + sb1);
        CP_COMMIT();
    };

    const int niter = K / 32;
    issue_loads(0);

    const int arow = warp_m * 64 + (lane & 15);
    const int acolh = (lane >> 4) * 8;
    const int brow = warp_n * 32 + (lane & 7);
    const int bcolh = ((lane >> 3) & 1) * 8;

    for (int it = 0; it < niter; it++) {
        if (it + 1 < niter) {
            issue_loads(it + 1);
            CP_WAIT(1);
        } else {
            CP_WAIT(0);
        }
        __syncthreads();

        const uint32_t b = sb + (it & 1) * MM_BUF;
#pragma unroll
        for (int ks = 0; ks < 32; ks += 16) {
            uint32_t ah[4][4], al[4][4], bh[4][2], bl[4][2];
#pragma unroll
            for (int mt = 0; mt < 4; mt++) {
                uint32_t addr = b + (arow + mt * 16) * 80 + (acolh + ks) * 2;
                ldmatrix_x4(ah[mt], addr);
                ldmatrix_x4(al[mt], addr + MM_TILE);
            }
#pragma unroll
            for (int nt = 0; nt < 4; nt++) {
                uint32_t addr = b + 2 * MM_TILE + (brow + nt * 8) * 80 + (bcolh + ks) * 2;
                ldmatrix_x2(bh[nt], addr);
                ldmatrix_x2(bl[nt], addr + MM_TILE);
            }
#pragma unroll
            for (int mt = 0; mt < 4; mt++)
#pragma unroll
                for (int nt = 0; nt < 4; nt++) {
                    mma_bf16(acc[mt][nt], ah[mt], bh[nt]);
                    mma_bf16(acc[mt][nt], ah[mt], bl[nt]);
                    mma_bf16(acc[mt][nt], al[mt], bh[nt]);
                }
        }
        __syncthreads();
    }

    const int tr = lane >> 2, tc = (lane & 3) * 2;
#pragma unroll
    for (int mt = 0; mt < 4; mt++) {
#pragma unroll
        for (int nt = 0; nt < 4; nt++) {
            int row = m0 + warp_m * 64 + mt * 16 + tr;
            int col = n0 + warp_n * 32 + nt * 8 + tc;
            *(float2*)&C[(size_t)row * N + col] =
                make_float2(acc[mt][nt][0], acc[mt][nt][1]);
            *(float2*)&C[(size_t)(row + 8) * N + col] =
                make_float2(acc[mt][nt][2], acc[mt][nt][3]);
        }
    }
}

// ===========================================================================
// RoPE, half-split pairing, REVERSED rotation (verified correct)
// ===========================================================================
__global__ void rope_rev_kernel(float* __restrict__ qkv,
                                const int* __restrict__ start_pos)
{
    const int half = DD / 2;
    int idx = blockIdx.x * blockDim.x + threadIdx.x;
    int total = NTOK * HH * half;
    if (idx >= total) return;

    int i = idx % half;
    int h = (idx / half) % HH;
    int n = idx / (half * HH);
    int t = n % TT;

    double pos = (double)(*start_pos + t);
    double inv_freq = exp2(-(double)i * (13.287712379549449 / 64.0));
    double ang = pos * inv_freq;
    const double TWOPI = 6.283185307179586476925286766559;
    ang -= floor(ang / TWOPI) * TWOPI;
    float c, s;
    sincosf((float)ang, &c, &s);

    float* qrow = qkv + (size_t)n * C3 + h * DD;
    float* krow = qrow + CC;

    float q1 = qrow[i], q2 = qrow[i + half];
    qrow[i]        =  q1 * c + q2 * s;
    qrow[i + half] = -q1 * s + q2 * c;

    float k1 = krow[i], k2 = krow[i + half];
    krow[i]        =  k1 * c + k2 * s;
    krow[i + half] = -k1 * s + k2 * c;
}

// ===========================================================================
// Tensor-core causal flash attention (hi/lo bf16, 3-term QK and PV).
// FMA-pipe fast_exp (no MUFU). Writes proj-GEMM inputs (ah, al) directly.
// Block: 128 thr (4 warps). Q tile 64 rows, KV tiles 64.
// ===========================================================================
#define FA_PD 136
#define FA_TILE (64 * FA_PD * 2)     // 17408 B
#define FA_SMEM (6 * FA_TILE)        // 104448 B

__device__ __forceinline__ void split_store8(char* ph, float4 v) {
    __nv_bfloat16 h0 = __float2bfloat16_rn(v.x), h1 = __float2bfloat16_rn(v.y);
    __nv_bfloat16 h2 = __float2bfloat16_rn(v.z), h3 = __float2bfloat16_rn(v.w);
    __nv_bfloat16 l0 = __float2bfloat16_rn(v.x - __bfloat162float(h0));
    __nv_bfloat16 l1 = __float2bfloat16_rn(v.y - __bfloat162float(h1));
    __nv_bfloat16 l2 = __float2bfloat16_rn(v.z - __bfloat162float(h2));
    __nv_bfloat16 l3 = __float2bfloat16_rn(v.w - __bfloat162float(h3));
    ((__nv_bfloat162*)ph)[0] = __nv_bfloat162(h0, h1);
    ((__nv_bfloat162*)ph)[1] = __nv_bfloat162(h2, h3);
    ((__nv_bfloat162*)(ph + FA_TILE))[0] = __nv_bfloat162(l0, l1);
    ((__nv_bfloat162*)(ph + FA_TILE))[1] = __nv_bfloat162(l2, l3);
}
__device__ __forceinline__ void store_hilo2(
    __nv_bfloat16* hi, __nv_bfloat16* lo, size_t idx, float a, float b)
{
    __nv_bfloat16 ha = __float2bfloat16_rn(a), hb = __float2bfloat16_rn(b);
    *(__nv_bfloat162*)(hi + idx) = __nv_bfloat162(ha, hb);
    *(__nv_bfloat162*)(lo + idx) = __nv_bfloat162(
        __float2bfloat16_rn(a - __bfloat162float(ha)),
        __float2bfloat16_rn(b - __bfloat162float(hb)));
}

__global__ __launch_bounds__(128) void attn_tc(
    const float* __restrict__ qkv,
    __nv_bfloat16* __restrict__ oh, __nv_bfloat16* __restrict__ ol)
{
    extern __shared__ __align__(16) char smem[];
    const uint32_t sb = smem_to_u32(smem);
    const uint32_t sQh = sb;
    const uint32_t sKh = sb + 2 * FA_TILE;
    const uint32_t sVh = sb + 4 * FA_TILE;

    const int tid = threadIdx.x, lane = tid & 31, w = tid >> 5;
    const int q0 = ((int)gridDim.x - 1 - (int)blockIdx.x) * 64;
    const int bh = blockIdx.y;
    const int b = bh >> 4, h = bh & 15;

    const float scale = 0.08838834764831845f;
    const float* Qg = qkv + (size_t)(b * TT + q0) * C3 + h * DD;
    const float* Kg = qkv + (size_t)(b * TT) * C3 + CC + h * DD;
    const float* Vg = qkv + (size_t)(b * TT) * C3 + 2 * CC + h * DD;

#pragma unroll
    for (int i = 0; i < 16; i++) {
        int idx = tid + i * 128;
        int row = idx >> 5, c4 = (idx & 31) << 2;
        float4 v = *(const float4*)&Qg[(size_t)row * C3 + c4];
        v.x *= scale; v.y *= scale; v.z *= scale; v.w *= scale;
        split_store8(smem + 0 * FA_TILE + row * 272 + c4 * 2, v);
    }

    float o[16][4];
#pragma unroll
    for (int i = 0; i < 16; i++)
#pragma unroll
        for (int j = 0; j < 4; j++) o[i][j] = 0.f;
    float m0 = -1e30f, m1 = -1e30f, l0 = 0.f, l1 = 0.f;

    const uint32_t qa = sQh + (w * 16 + (lane & 15)) * 272 + (lane >> 4) * 16;
    const int krow_off = (lane & 7) + 8 * (lane >> 4);
    const int kcol_off = 8 * ((lane >> 3) & 1);
    const int vrow_off = (lane & 7) + 8 * ((lane >> 3) & 1);
    const int vcol_off = 8 * (lane >> 4);

    const int kv_end = q0 + 64;
    for (int j0 = 0; j0 < kv_end; j0 += 64) {
        __syncthreads();
#pragma unroll
        for (int i = 0; i < 16; i++) {
            int idx = tid + i * 128;
            int row = idx >> 5, c4 = (idx & 31) << 2;
            float4 kv4 = *(const float4*)&Kg[(size_t)(j0 + row) * C3 + c4];
            split_store8(smem + 2 * FA_TILE + row * 272 + c4 * 2, kv4);
            float4 vv4 = *(const float4*)&Vg[(size_t)(j0 + row) * C3 + c4];
            split_store8(smem + 4 * FA_TILE + row * 272 + c4 * 2, vv4);
        }
        __syncthreads();

        // ---- S = Qs @ K^T (3-term) ----
        float s[8][4];
#pragma unroll
        for (int nt = 0; nt < 8; nt++)
#pragma unroll
            for (int j = 0; j < 4; j++) s[nt][j] = 0.f;

#pragma unroll
        for (int ks = 0; ks < 8; ks++) {
            uint32_t aqh[4], aql[4];
            uint32_t qaddr = qa + ks * 32;
            ldmatrix_x4(aqh, qaddr);
            ldmatrix_x4(aql, qaddr + FA_TILE);
#pragma unroll
            for (int nt2 = 0; nt2 < 4; nt2++) {
                uint32_t bkh[4], bkl[4];
                uint32_t kaddr = sKh + (nt2 * 16 + krow_off) * 272 + (ks * 16 + kcol_off) * 2;
                ldmatrix_x4(bkh, kaddr);
                ldmatrix_x4(bkl, kaddr + FA_TILE);
                mma_bf16(s[2*nt2],   aqh, &bkh[0]);
                mma_bf16(s[2*nt2],   aqh, &bkl[0]);
                mma_bf16(s[2*nt2],   aql, &bkh[0]);
                mma_bf16(s[2*nt2+1], aqh, &bkh[2]);
                mma_bf16(s[2*nt2+1], aqh, &bkl[2]);
                mma_bf16(s[2*nt2+1], aql, &bkh[2]);
            }
        }

        // causal mask (diagonal tile only)
        if (j0 == q0) {
            int rl0 = w * 16 + (lane >> 2);
            int cb = (lane & 3) * 2;
#pragma unroll
            for (int nt = 0; nt < 8; nt++) {
                int cg = nt * 8 + cb;
                if (cg     > rl0)     s[nt][0] = -1e30f;
                if (cg + 1 > rl0)     s[nt][1] = -1e30f;
                if (cg     > rl0 + 8) s[nt][2] = -1e30f;
                if (cg + 1 > rl0 + 8) s[nt][3] = -1e30f;
            }
        }

        // ---- online softmax (fast_exp, FMA pipe) ----
        float mx0 = m0, mx1 = m1;
#pragma unroll
        for (int nt = 0; nt < 8; nt++) {
            mx0 = fmaxf(mx0, fmaxf(s[nt][0], s[nt][1]));
            mx1 = fmaxf(mx1, fmaxf(s[nt][2], s[nt][3]));
        }
        mx0 = fmaxf(mx0, __shfl_xor_sync(0xffffffffu, mx0, 1));
        mx0 = fmaxf(mx0, __shfl_xor_sync(0xffffffffu, mx0, 2));
        mx1 = fmaxf(mx1, __shfl_xor_sync(0xffffffffu, mx1, 1));
        mx1 = fmaxf(mx1, __shfl_xor_sync(0xffffffffu, mx1, 2));

        float c0 = fast_exp(m0 - mx0), c1 = fast_exp(m1 - mx1);
        m0 = mx0; m1 = mx1;
        l0 *= c0; l1 *= c1;
#pragma unroll
        for (int dnt = 0; dnt < 16; dnt++) {
            o[dnt][0] *= c0; o[dnt][1] *= c0;
            o[dnt][2] *= c1; o[dnt][3] *= c1;
        }

        uint32_t pAh[4][4], pAl[4][4];
        float rs0 = 0.f, rs1 = 0.f;
#pragma unroll
        for (int nt = 0; nt < 8; nt++) {
            float p0 = fast_exp(s[nt][0] - m0);
            float p1 = fast_exp(s[nt][1] - m0);
            float p2 = fast_exp(s[nt][2] - m1);
            float p3 = fast_exp(s[nt][3] - m1);
            rs0 += p0 + p1;
            rs1 += p2 + p3;
            __nv_bfloat16 h0 = __float2bfloat16_rn(p0), h1 = __float2bfloat16_rn(p1);
            __nv_bfloat16 h2 = __float2bfloat16_rn(p2), h3 = __float2bfloat16_rn(p3);
            int kk = nt >> 1, hf = (nt & 1) * 2;
            {
                __nv_bfloat162 t01(h0, h1), t23(h2, h3);
                pAh[kk][hf + 0] = *(uint32_t*)&t01;
                pAh[kk][hf + 1] = *(uint32_t*)&t23;
            }
            pAl[kk][hf + 0] = pack_bf16(p0 - __bfloat162float(h0),
                                        p1 - __bfloat162float(h1));
            pAl[kk][hf + 1] = pack_bf16(p2 - __bfloat162float(h2),
                                        p3 - __bfloat162float(h3));
        }
        l0 += rs0; l1 += rs1;

        // ---- O += P @ V (3-term) ----
#pragma unroll
        for (int kk = 0; kk < 4; kk++) {
#pragma unroll
            for (int dt2 = 0; dt2 < 8; dt2++) {
                uint32_t vh4[4], vl4[4];
                uint32_t vaddr = sVh + (kk * 16 + vrow_off) * 272 + (dt2 * 16 + vcol_off) * 2;
                ldmatrix_x4t(vh4, vaddr);
                ldmatrix_x4t(vl4, vaddr + FA_TILE);
                mma_bf16(o[2*dt2],   pAh[kk], &vh4[0]);
                mma_bf16(o[2*dt2],   pAh[kk], &vl4[0]);
                mma_bf16(o[2*dt2],   pAl[kk], &vh4[0]);
                mma_bf16(o[2*dt2+1], pAh[kk], &vh4[2]);
                mma_bf16(o[2*dt2+1], pAh[kk], &vl4[2]);
                mma_bf16(o[2*dt2+1], pAl[kk], &vh4[2]);
            }
        }
    }

    // finalize: write bf16 hi/lo directly (proj GEMM inputs)
    l0 += __shfl_xor_sync(0xffffffffu, l0, 1);
    l0 += __shfl_xor_sync(0xffffffffu, l0, 2);
    l1 += __shfl_xor_sync(0xffffffffu, l1, 1);
    l1 += __shfl_xor_sync(0xffffffffu, l1, 2);
    const float inv0 = 1.f / l0, inv1 = 1.f / l1;

    const int row0 = q0 + w * 16 + (lane >> 2);
    const int c2 = (lane & 3) * 2;
    const size_t base0 = (size_t)(b * TT + row0) * CC + h * DD;
    const size_t base1 = base0 + (size_t)8 * CC;
#pragma unroll
    for (int dnt = 0; dnt < 16; dnt++) {
        int d = dnt * 8 + c2;
        store_hilo2(oh, ol, base0 + d, o[dnt][0] * inv0, o[dnt][1] * inv0);
        store_hilo2(oh, ol, base1 + d, o[dnt][2] * inv1, o[dnt][3] * inv1);
    }
}

// ===========================================================================
extern "C" void kernel_launch(void* const* d_in, const int* in_sizes, int n_in,
                              void* d_out, int out_size)
{
    const float* x = nullptr;
    const float* Wqkv = nullptr;
    const float* Wproj = nullptr;
    const int* start_pos = nullptr;
    for (int i = 0; i < n_in; i++) {
        long long sz = in_sizes[i];
        if (sz == (long long)NTOK * CC)      x = (const float*)d_in[i];
        else if (sz == (long long)C3 * CC)   Wqkv = (const float*)d_in[i];
        else if (sz == (long long)CC * CC)   Wproj = (const float*)d_in[i];
        else if (sz == 1)                    start_pos = (const int*)d_in[i];
    }
    if (n_in != 4 || !x || !Wqkv || !Wproj || !start_pos ||
        out_size != NTOK * CC)
        return;

    float* out = (float*)d_out;

    void* p;
    cudaGetSymbolAddress(&p, g_qkv);  float* qkv  = (float*)p;
    cudaGetSymbolAddress(&p, g_xh);   __nv_bfloat16* xh  = (__nv_bfloat16*)p;
    cudaGetSymbolAddress(&p, g_xl);   __nv_bfloat16* xl  = (__nv_bfloat16*)p;
    cudaGetSymbolAddress(&p, g_wqh);  __nv_bfloat16* wqh = (__nv_bfloat16*)p;
    cudaGetSymbolAddress(&p, g_wql);  __nv_bfloat16* wql = (__nv_bfloat16*)p;
    cudaGetSymbolAddress(&p, g_wph);  __nv_bfloat16* wph = (__nv_bfloat16*)p;
    cudaGetSymbolAddress(&p, g_wpl);  __nv_bfloat16* wpl = (__nv_bfloat16*)p;
    cudaGetSymbolAddress(&p, g_ah);   __nv_bfloat16* ah  = (__nv_bfloat16*)p;
    cudaGetSymbolAddress(&p, g_al);   __nv_bfloat16* al  = (__nv_bfloat16*)p;

    cudaFuncSetAttribute(gemm_mma, cudaFuncAttributeMaxDynamicSharedMemorySize, MM_SMEM);
    cudaFuncSetAttribute(attn_tc,  cudaFuncAttributeMaxDynamicSharedMemorySize, FA_SMEM);

    // 0) split inputs to bf16 hi/lo
    {
        int n4;
        n4 = NTOK * CC / 4; split_bf16<<<(n4 + 255)/256, 256>>>(x,     xh,  xl,  n4);
        n4 = C3 * CC / 4;   split_bf16<<<(n4 + 255)/256, 256>>>(Wqkv,  wqh, wql, n4);
        n4 = CC * CC / 4;   split_bf16<<<(n4 + 255)/256, 256>>>(Wproj, wph, wpl, n4);
    }

    // 1) qkv = x @ Wqkv^T  (tensor cores)
    gemm_mma<<<dim3(C3 / 128, NTOK / 128), 256, MM_SMEM>>>(
        xh, xl, wqh, wql, qkv, NTOK, C3, CC);

    // 2) RoPE (reversed rotation — verified)
    {
        int total = NTOK * HH * (DD / 2);
        rope_rev_kernel<<<(total + 255) / 256, 256>>>(qkv, start_pos);
    }

    // 3) causal flash attention (tensor cores, fast_exp) -> ah/al directly
    attn_tc<<<dim3(TT / 64, BB * HH), 128, FA_SMEM>>>(qkv, ah, al);

    // 4) out = attn @ Wproj^T  (tensor cores)
    gemm_mma<<<dim3(CC / 128, NTOK / 128), 256, MM_SMEM>>>(
        ah, al, wph, wpl, out, NTOK, CC, CC);
}